// round 8
// baseline (speedup 1.0000x reference)
#include <cuda_runtime.h>

// out[b,h,w] = sum_c x[b,h,w,c] * mask[h%8,w%8,c],
// mask = sigmoid(12*(sigmoid(5*w) - thresh)), x: (32,512,512,4) fp32 NHWC.
//
// Plateau established: DRAM sits at 65-68% (~5.4 TB/s) across occ 41-86%,
// L1 21-80%, MLP 4-8, with/without .cs -- effective HBM ceiling for this
// 4:1 read:write single-touch mix. R8 = union of best-measured attributes:
//   - R4 dense 512B warp loads, one mask float4/thread, plain LDG (no .cs,
//     which cost 1.4% in R7)
//   - regs-light paired front-batch: both iterations' 4 loads issued before
//     either iteration's stores (MLP 8 in flight, ~36 regs -> R4 occupancy)

#define PMASK_SLOPE 5.0f
#define SAMPLE_SLOPE 12.0f

#define NPIX        (32 * 512 * 512)      // 8,388,608 pixels
#define NTHREADS    (2048 * 256)          // 524,288
#define PIX_PER_IT  (NTHREADS * 4)        // 2,097,152 (mult of 4096: h%8 invariant)
#define NITERS      (NPIX / PIX_PER_IT)   // 4

__device__ __forceinline__ float sigmoidf(float z) {
    return 1.0f / (1.0f + __expf(-z));
}

__device__ __forceinline__ float dot4(float4 v, float4 m) {
    return v.x * m.x + v.y * m.y + v.z * m.z + v.w * m.w;
}

__global__ void __launch_bounds__(256)
probmask_kernel(const float4* __restrict__ x,
                const float4* __restrict__ wv,
                const float4* __restrict__ tv,
                float* __restrict__ out)
{
    __shared__ float4 smask[64];   // [h8*8 + w8] -> per-channel mask

    int tid = threadIdx.x;
    if (tid < 64) {
        float4 w4 = wv[tid];
        float4 t4 = tv[tid];
        float4 m;
        m.x = sigmoidf(SAMPLE_SLOPE * (sigmoidf(PMASK_SLOPE * w4.x) - t4.x));
        m.y = sigmoidf(SAMPLE_SLOPE * (sigmoidf(PMASK_SLOPE * w4.y) - t4.y));
        m.z = sigmoidf(SAMPLE_SLOPE * (sigmoidf(PMASK_SLOPE * w4.z) - t4.z));
        m.w = sigmoidf(SAMPLE_SLOPE * (sigmoidf(PMASK_SLOPE * w4.w) - t4.w));
        smask[tid] = m;
    }
    __syncthreads();

    int lane  = tid & 31;
    int gwarp = (blockIdx.x * blockDim.x + tid) >> 5;   // 0..16383
    int base0 = gwarp << 7;                             // warp's first pixel (mult of 128)

    // h%8 warp-uniform and iteration-invariant; w%8 = lane&7.
    int h8 = (base0 >> 9) & 7;
    float4 m = smask[(h8 << 3) + (lane & 7)];

    #pragma unroll
    for (int it = 0; it < NITERS; it += 2) {
        int pa = base0 + it * PIX_PER_IT + lane;
        int pb = pa + PIX_PER_IT;

        // 8 dense 512B warp loads in flight before any store.
        float4 a0 = x[pa +  0];
        float4 a1 = x[pa + 32];
        float4 a2 = x[pa + 64];
        float4 a3 = x[pa + 96];
        float4 b0 = x[pb +  0];
        float4 b1 = x[pb + 32];
        float4 b2 = x[pb + 64];
        float4 b3 = x[pb + 96];

        out[pa +  0] = dot4(a0, m);
        out[pa + 32] = dot4(a1, m);
        out[pa + 64] = dot4(a2, m);
        out[pa + 96] = dot4(a3, m);
        out[pb +  0] = dot4(b0, m);
        out[pb + 32] = dot4(b1, m);
        out[pb + 64] = dot4(b2, m);
        out[pb + 96] = dot4(b3, m);
    }
}

extern "C" void kernel_launch(void* const* d_in, const int* in_sizes, int n_in,
                              void* d_out, int out_size)
{
    const float4* x  = (const float4*)d_in[0];
    const float4* wv = (const float4*)d_in[1];
    const float4* tv = (const float4*)d_in[2];
    float* out = (float*)d_out;

    probmask_kernel<<<NTHREADS / 256, 256>>>(x, wv, tv, out);
}

// round 9
// speedup vs baseline: 1.0167x; 1.0167x over previous
#include <cuda_runtime.h>

// out[b,h,w] = sum_c x[b,h,w,c] * mask[h%8,w%8,c],
// mask = sigmoid(12*(sigmoid(5*w) - thresh)), x: (32,512,512,4) fp32 NHWC.
//
// R9 theory: the 65-68% DRAM "plateau" is wave-quantization tail, not an HBM
// ceiling. R8: 2048 blocks x 4 work-units on 888 slots -> makespan 12 units vs
// 9.2 ideal (~30% tail idle). Fix: one work-unit per block, 8192 blocks on
// ~1184 slots -> makespan 7 vs 6.92 ideal (~1% tail). Memory pattern unchanged
// from R4 (dense 512B warp loads, one mask float4 per thread, plain LDG).

#define PMASK_SLOPE 5.0f
#define SAMPLE_SLOPE 12.0f

#define NPIX    (32 * 512 * 512)   // 8,388,608 pixels
#define NBLOCKS (NPIX / (256 * 4)) // 8192: each 256-thread block covers 1024 px

__device__ __forceinline__ float sigmoidf(float z) {
    return 1.0f / (1.0f + __expf(-z));
}

__device__ __forceinline__ float dot4(float4 v, float4 m) {
    return v.x * m.x + v.y * m.y + v.z * m.z + v.w * m.w;
}

__global__ void __launch_bounds__(256)
probmask_kernel(const float4* __restrict__ x,
                const float4* __restrict__ wv,
                const float4* __restrict__ tv,
                float* __restrict__ out)
{
    __shared__ float4 smask[64];   // [h8*8 + w8] -> per-channel mask

    int tid = threadIdx.x;
    if (tid < 64) {
        float4 w4 = wv[tid];
        float4 t4 = tv[tid];
        float4 m;
        m.x = sigmoidf(SAMPLE_SLOPE * (sigmoidf(PMASK_SLOPE * w4.x) - t4.x));
        m.y = sigmoidf(SAMPLE_SLOPE * (sigmoidf(PMASK_SLOPE * w4.y) - t4.y));
        m.z = sigmoidf(SAMPLE_SLOPE * (sigmoidf(PMASK_SLOPE * w4.z) - t4.z));
        m.w = sigmoidf(SAMPLE_SLOPE * (sigmoidf(PMASK_SLOPE * w4.w) - t4.w));
        smask[tid] = m;
    }
    __syncthreads();

    int lane  = tid & 31;
    int gwarp = (blockIdx.x * blockDim.x + tid) >> 5;   // global warp id
    int base0 = gwarp << 7;                             // warp's first pixel (mult of 128)

    // Warp tile = 128 consecutive pixels in one row-group: h%8 warp-uniform,
    // w%8 of lane's pixels (stride 32) = lane & 7.
    int h8 = (base0 >> 9) & 7;
    float4 m = smask[(h8 << 3) + (lane & 7)];

    int p = base0 + lane;

    // 4 dense 512B warp loads; every LDG.128 touches 4 cache lines exactly.
    float4 v0 = x[p +  0];
    float4 v1 = x[p + 32];
    float4 v2 = x[p + 64];
    float4 v3 = x[p + 96];

    out[p +  0] = dot4(v0, m);
    out[p + 32] = dot4(v1, m);
    out[p + 64] = dot4(v2, m);
    out[p + 96] = dot4(v3, m);
}

extern "C" void kernel_launch(void* const* d_in, const int* in_sizes, int n_in,
                              void* d_out, int out_size)
{
    const float4* x  = (const float4*)d_in[0];
    const float4* wv = (const float4*)d_in[1];
    const float4* tv = (const float4*)d_in[2];
    float* out = (float*)d_out;

    probmask_kernel<<<NBLOCKS, 256>>>(x, wv, tv, out);
}

// round 10
// speedup vs baseline: 1.0894x; 1.0715x over previous
#include <cuda_runtime.h>

// out[b,h,w] = sum_c x[b,h,w,c] * mask[h%8,w%8,c],
// mask = sigmoid(12*(sigmoid(5*w) - thresh)), x: (32,512,512,4) fp32 NHWC.
//
// R9 (8192 x 256-thread single-unit blocks) lifted DRAM 66.8->70.5%, 26.27us:
// wave-quantization was the plateau. R10 halves scheduling granularity again:
// 16384 x 128-thread blocks (16 resident CTAs/SM, same 2048 threads/SM), each
// block = exactly one 512-pixel image row (h%8 block-uniform). Memory pattern
// unchanged: dense 512B warp loads, one register mask float4 per thread.

#define PMASK_SLOPE 5.0f
#define SAMPLE_SLOPE 12.0f

#define NPIX    (32 * 512 * 512)    // 8,388,608 pixels
#define NBLOCKS (NPIX / 512)        // 16384 blocks, one row each

__device__ __forceinline__ float sigmoidf(float z) {
    return 1.0f / (1.0f + __expf(-z));
}

__device__ __forceinline__ float dot4(float4 v, float4 m) {
    return v.x * m.x + v.y * m.y + v.z * m.z + v.w * m.w;
}

__global__ void __launch_bounds__(128)
probmask_kernel(const float4* __restrict__ x,
                const float4* __restrict__ wv,
                const float4* __restrict__ tv,
                float* __restrict__ out)
{
    __shared__ float4 smask[64];   // [h8*8 + w8] -> per-channel mask

    int tid = threadIdx.x;
    if (tid < 64) {
        float4 w4 = wv[tid];
        float4 t4 = tv[tid];
        float4 m;
        m.x = sigmoidf(SAMPLE_SLOPE * (sigmoidf(PMASK_SLOPE * w4.x) - t4.x));
        m.y = sigmoidf(SAMPLE_SLOPE * (sigmoidf(PMASK_SLOPE * w4.y) - t4.y));
        m.z = sigmoidf(SAMPLE_SLOPE * (sigmoidf(PMASK_SLOPE * w4.z) - t4.z));
        m.w = sigmoidf(SAMPLE_SLOPE * (sigmoidf(PMASK_SLOPE * w4.w) - t4.w));
        smask[tid] = m;
    }
    __syncthreads();

    int lane = tid & 31;
    int warp = tid >> 5;                       // 0..3
    int row0 = blockIdx.x << 9;                // block's first pixel (one row)
    int base0 = row0 + (warp << 7);            // warp's 128-pixel tile

    // h%8 is uniform for the whole block (one image row); w%8 = lane&7
    // for this lane's pixels (stride 32 within the warp tile).
    int h8 = (row0 >> 9) & 7;
    float4 m = smask[(h8 << 3) + (lane & 7)];

    int p = base0 + lane;

    // 4 dense 512B warp loads; every LDG.128 touches exactly 4 cache lines.
    float4 v0 = x[p +  0];
    float4 v1 = x[p + 32];
    float4 v2 = x[p + 64];
    float4 v3 = x[p + 96];

    out[p +  0] = dot4(v0, m);
    out[p + 32] = dot4(v1, m);
    out[p + 64] = dot4(v2, m);
    out[p + 96] = dot4(v3, m);
}

extern "C" void kernel_launch(void* const* d_in, const int* in_sizes, int n_in,
                              void* d_out, int out_size)
{
    const float4* x  = (const float4*)d_in[0];
    const float4* wv = (const float4*)d_in[1];
    const float4* tv = (const float4*)d_in[2];
    float* out = (float*)d_out;

    probmask_kernel<<<NBLOCKS, 128>>>(x, wv, tv, out);
}